// round 9
// baseline (speedup 1.0000x reference)
#include <cuda_runtime.h>
#include <cuda_fp16.h>
#include <cstdint>

// Problem constants: x [8192,512] fp32, codebook [8192,512] fp32.
#define DIMV    512
#define ROW_F4  128
#define KCB     8192
#define NROWSC  8192
#define BM      128
#define BN      128
#define KSTAGES 8             // K = 512 fp8, 64 per stage
#define NBUF    4
#define STAGEB  16384         // A 8KB + B 8KB per stage (64B rows, 128 rows each)
#define SMEMSZ  (NBUF*STAGEB + 1024)
#define TILES8  (KCB / 8)     // 1024 eight-code tiles per row
#define EPS     24.0f         // pruning slack (~7.4 sigma of fp8 score error)

__device__ __align__(16) uint8_t g_x8[NROWSC * DIMV];
__device__ __align__(16) uint8_t g_e8[KCB * DIMV];
__device__ float g_esq[KCB];
__device__ float g_tileMax[NROWSC * TILES8];   // 32MB

__device__ __forceinline__ uint32_t smem_u32(const void* p) {
    uint32_t a;
    asm("{ .reg .u64 t; cvta.to.shared.u64 t, %1; cvt.u32.u64 %0, t; }" : "=r"(a) : "l"(p));
    return a;
}
__device__ __forceinline__ void cpasync16(uint32_t dst, const void* src) {
    asm volatile("cp.async.cg.shared.global [%0], [%1], 16;"
                 :: "r"(dst), "l"(__cvta_generic_to_global(src)) : "memory");
}
__device__ __forceinline__ void ldsm4(uint32_t* r, uint32_t addr) {
    asm volatile("ldmatrix.sync.aligned.m8n8.x4.shared.b16 {%0,%1,%2,%3}, [%4];"
                 : "=r"(r[0]), "=r"(r[1]), "=r"(r[2]), "=r"(r[3]) : "r"(addr));
}
__device__ __forceinline__ void mmafp8(float* d, const uint32_t* a,
                                       uint32_t b0, uint32_t b1) {
    asm volatile(
        "mma.sync.aligned.m16n8k32.row.col.f32.e4m3.e4m3.f32 "
        "{%0,%1,%2,%3}, {%4,%5,%6,%7}, {%8,%9}, {%0,%1,%2,%3};"
        : "+f"(d[0]), "+f"(d[1]), "+f"(d[2]), "+f"(d[3])
        : "r"(a[0]), "r"(a[1]), "r"(a[2]), "r"(a[3]), "r"(b0), "r"(b1));
}
__device__ __forceinline__ uint32_t fp8x4(float4 v) {
    uint16_t lo, hi;
    asm("cvt.rn.satfinite.e4m3x2.f32 %0, %1, %2;" : "=h"(lo) : "f"(v.y), "f"(v.x));
    asm("cvt.rn.satfinite.e4m3x2.f32 %0, %1, %2;" : "=h"(hi) : "f"(v.w), "f"(v.z));
    return (uint32_t)lo | ((uint32_t)hi << 16);
}

// ---------------------------------------------------------------------------
__global__ void conv_x_kernel(const float4* __restrict__ x4) {
    int row  = blockIdx.x * 8 + (threadIdx.x >> 5);
    int lane = threadIdx.x & 31;
    const float4* p = x4 + (size_t)row * ROW_F4;
    uint32_t* o = (uint32_t*)(g_x8 + (size_t)row * DIMV);
#pragma unroll
    for (int c = 0; c < 4; ++c) o[c * 32 + lane] = fp8x4(p[c * 32 + lane]);
}

__global__ void conv_e_kernel(const float4* __restrict__ e4) {
    int row  = blockIdx.x * 8 + (threadIdx.x >> 5);
    int lane = threadIdx.x & 31;
    const float4* p = e4 + (size_t)row * ROW_F4;
    uint32_t* o = (uint32_t*)(g_e8 + (size_t)row * DIMV);
    float s = 0.f;
#pragma unroll
    for (int c = 0; c < 4; ++c) {
        float4 v = p[c * 32 + lane];
        s += v.x * v.x + v.y * v.y + v.z * v.z + v.w * v.w;
        o[c * 32 + lane] = fp8x4(v);
    }
#pragma unroll
    for (int off = 16; off; off >>= 1) s += __shfl_down_sync(0xFFFFFFFFu, s, off);
    if (lane == 0) g_esq[row] = s;
}

// ---------------------------------------------------------------------------
// Pass 1: fp8 e4m3 GEMM, per-(row, 8-code tile) approx-score maxima.
// grid (64 ntiles, 64 mtiles), 128 threads = 4 warps (2M x 2N), warp 64x64.
// Stage = K 64 fp8 (64B rows, 128 rows per operand = 8KB each).
// ---------------------------------------------------------------------------
__global__ __launch_bounds__(128, 2) void vq_mma() {
    extern __shared__ char smem[];
    const uint32_t sb = smem_u32(smem);
    float* esq_s = (float*)(smem + NBUF * STAGEB);

    const int tid = threadIdx.x, lane = tid & 31, wid = tid >> 5;
    const int wm = wid >> 1, wn = wid & 1;
    const int mBase = blockIdx.y * BM, nBase = blockIdx.x * BN;

    if (tid < 32) ((float4*)esq_s)[tid] = ((const float4*)(g_esq + nBase))[tid];

    // cp.async: 1024 16B chunks/stage (512 A + 512 B), 8 per thread.
    const int rr = tid >> 2, cI = tid & 3;   // rr 0..31, cI 0..3

#define ISSUE(s)                                                               \
    {                                                                          \
        const int k0_ = (s) * 64;                                              \
        const uint32_t st_ = sb + ((s) & 3) * STAGEB;                          \
        _Pragma("unroll")                                                      \
        for (int j = 0; j < 4; ++j) {                                          \
            const int r_ = j * 32 + rr;                                        \
            const uint32_t d_ = (uint32_t)r_ * 64 + ((cI ^ ((r_ >> 1) & 3)) << 4); \
            cpasync16(st_ + d_,        g_x8 + (size_t)(mBase + r_) * DIMV + k0_ + cI * 16); \
            cpasync16(st_ + 8192 + d_, g_e8 + (size_t)(nBase + r_) * DIMV + k0_ + cI * 16); \
        }                                                                      \
        asm volatile("cp.async.commit_group;" ::: "memory");                   \
    }

    float acc[4][8][4];
#pragma unroll
    for (int a = 0; a < 4; ++a)
#pragma unroll
        for (int b = 0; b < 8; ++b)
#pragma unroll
            for (int c = 0; c < 4; ++c) acc[a][b][c] = 0.f;

    // ldsm bases: swizzle group depends only on (lane&15).
    const int l15 = lane & 15, hi16 = lane >> 4;
    const uint32_t swz = (uint32_t)((l15 >> 1) & 3);
    uint32_t aBase[4], bBase[4];
#pragma unroll
    for (int mt = 0; mt < 4; ++mt)
        aBase[mt] = (uint32_t)(wm * 64 + mt * 16 + l15) * 64;
#pragma unroll
    for (int nt2 = 0; nt2 < 4; ++nt2)
        bBase[nt2] = 8192u + (uint32_t)(wn * 64 + nt2 * 16 + l15) * 64;

    ISSUE(0); ISSUE(1); ISSUE(2);

    for (int s = 0; s < KSTAGES; ++s) {
        if (s + 3 < KSTAGES)
            asm volatile("cp.async.wait_group 2;" ::: "memory");
        else
            asm volatile("cp.async.wait_group 0;" ::: "memory");
        __syncthreads();

        const uint32_t st = sb + (s & 3) * STAGEB;
#pragma unroll
        for (int kk = 0; kk < 2; ++kk) {
            // 16B chunk = 16 fp8 (k-width 16): lanes 0-15 chunk 2kk, 16-31 chunk 2kk+1
            const uint32_t coloff = (((uint32_t)(kk * 2 + hi16) ^ swz) & 3) << 4;
            uint32_t a[4][4], b[4][4];
#pragma unroll
            for (int mt = 0; mt < 4; ++mt) ldsm4(a[mt], st + aBase[mt] + coloff);
#pragma unroll
            for (int nt2 = 0; nt2 < 4; ++nt2) ldsm4(b[nt2], st + bBase[nt2] + coloff);
#pragma unroll
            for (int mt = 0; mt < 4; ++mt)
#pragma unroll
                for (int nt = 0; nt < 8; ++nt) {
                    const int nt2 = nt >> 1, od = nt & 1;
                    mmafp8(acc[mt][nt], a[mt], b[nt2][od], b[nt2][2 + od]);
                }
        }
        if (s + 3 < KSTAGES) ISSUE(s + 3);
    }
#undef ISSUE

    // Epilogue: per-(row, 8-code tile) max of approx score (quad-reduced).
    const int q = lane & 3, qr = lane >> 2;
#pragma unroll
    for (int mt = 0; mt < 4; ++mt) {
#pragma unroll
        for (int h = 0; h < 2; ++h) {
            const int rowG = mBase + wm * 64 + mt * 16 + h * 8 + qr;
            float* dst = g_tileMax + (size_t)rowG * TILES8 + blockIdx.x * 16 + wn * 8;
#pragma unroll
            for (int nt = 0; nt < 8; ++nt) {
                const int col = wn * 64 + nt * 8 + q * 2;
                float s0 = 2.f * acc[mt][nt][h * 2 + 0] - esq_s[col];
                float s1 = 2.f * acc[mt][nt][h * 2 + 1] - esq_s[col + 1];
                float bv = fmaxf(s0, s1);
                bv = fmaxf(bv, __shfl_xor_sync(0xFFFFFFFFu, bv, 1));
                bv = fmaxf(bv, __shfl_xor_sync(0xFFFFFFFFu, bv, 2));
                if (q == 0) dst[nt] = bv;
            }
        }
    }
}

// ---------------------------------------------------------------------------
// Pass 2: 2 warps per row (each owns 512 tiles). Scan tile maxima, exact fp32
// rescore of candidates, argmax (ties -> smallest idx), gather + index.
// 256 threads = 8 warps = 4 rows per CTA.
// ---------------------------------------------------------------------------
__global__ __launch_bounds__(256) void rescore_kernel(
        const float4* __restrict__ x4, const float4* __restrict__ e4,
        float* __restrict__ out, int nRows) {
    __shared__ float xs[4][DIMV];
    __shared__ float sMax[4][2];
    __shared__ float sBV[4][2];
    __shared__ int   sBI[4][2];

    const int tid = threadIdx.x, lane = tid & 31, wid = tid >> 5;
    const int rl = wid >> 1, half = wid & 1;
    const int row = blockIdx.x * 4 + rl;

    // Stage x: each warp loads its half of the row (64 f4).
    float4* xs4 = (float4*)xs[rl];
#pragma unroll
    for (int c = 0; c < 2; ++c)
        xs4[half * 64 + c * 32 + lane] =
            x4[(size_t)row * ROW_F4 + half * 64 + c * 32 + lane];

    // Load this warp's 512 tile maxima (4 f4 per lane), local max.
    const float4* tm4 = (const float4*)(g_tileMax + (size_t)row * TILES8);
    float4 tv[4];
    float m = -3.4e38f;
#pragma unroll
    for (int j = 0; j < 4; ++j) {
        tv[j] = tm4[half * 128 + j * 32 + lane];
        m = fmaxf(m, fmaxf(fmaxf(tv[j].x, tv[j].y), fmaxf(tv[j].z, tv[j].w)));
    }
#pragma unroll
    for (int off = 16; off; off >>= 1)
        m = fmaxf(m, __shfl_xor_sync(0xFFFFFFFFu, m, off));
    if (lane == 0) sMax[rl][half] = m;
    __syncthreads();
    const float thr = fmaxf(sMax[rl][0], sMax[rl][1]) - EPS;

    float bv = -3.4e38f; int bi = 0x7FFFFFFF;
    const int qq = lane & 3, code8 = lane >> 2;

#pragma unroll
    for (int j = 0; j < 4; ++j) {
        bool any = (tv[j].x >= thr) | (tv[j].y >= thr) |
                   (tv[j].z >= thr) | (tv[j].w >= thr);
        unsigned mask = __ballot_sync(0xFFFFFFFFu, any);
        while (mask) {
            const int src = __ffs(mask) - 1;
            mask &= mask - 1;
            float cc[4];
            cc[0] = __shfl_sync(0xFFFFFFFFu, tv[j].x, src);
            cc[1] = __shfl_sync(0xFFFFFFFFu, tv[j].y, src);
            cc[2] = __shfl_sync(0xFFFFFFFFu, tv[j].z, src);
            cc[3] = __shfl_sync(0xFFFFFFFFu, tv[j].w, src);
#pragma unroll
            for (int comp = 0; comp < 4; ++comp) {
                if (cc[comp] < thr) continue;
                const int t = (half * 128 + j * 32 + src) * 4 + comp;
                const int code = t * 8 + code8;   // 8 codes/tile, 4 lanes/code
                const float4* ep = e4 + (size_t)code * ROW_F4;
                float d = 0.f;
#pragma unroll
                for (int c = 0; c < 32; ++c) {
                    float4 ev = ep[qq * 32 + c];
                    float4 xv = xs4[qq * 32 + c];
                    d += ev.x * xv.x + ev.y * xv.y + ev.z * xv.z + ev.w * xv.w;
                }
                d += __shfl_xor_sync(0xFFFFFFFFu, d, 1);
                d += __shfl_xor_sync(0xFFFFFFFFu, d, 2);
                if (qq == 0) {
                    float s = 2.f * d - g_esq[code];
                    if (s > bv || (s == bv && code < bi)) { bv = s; bi = code; }
                }
            }
        }
    }

#pragma unroll
    for (int off = 16; off; off >>= 1) {
        float ov = __shfl_xor_sync(0xFFFFFFFFu, bv, off);
        int   oi = __shfl_xor_sync(0xFFFFFFFFu, bi, off);
        if (ov > bv || (ov == bv && oi < bi)) { bv = ov; bi = oi; }
    }
    if (lane == 0) { sBV[rl][half] = bv; sBI[rl][half] = bi; }
    __syncthreads();

    if (half == 0) {
        float v0 = sBV[rl][0], v1 = sBV[rl][1];
        int   i0 = sBI[rl][0], i1 = sBI[rl][1];
        int idx = (v1 > v0 || (v1 == v0 && i1 < i0)) ? i1 : i0;
        const float4* src = e4 + (size_t)idx * ROW_F4;
        float4* dst = (float4*)out + (size_t)row * ROW_F4;
#pragma unroll
        for (int c = 0; c < 4; ++c) dst[lane + 32 * c] = src[lane + 32 * c];
        if (lane == 0) out[(size_t)nRows * DIMV + row] = (float)idx;
    }
}

// ---------------------------------------------------------------------------
extern "C" void kernel_launch(void* const* d_in, const int* in_sizes, int n_in,
                              void* d_out, int out_size) {
    const float4* x4 = (const float4*)d_in[0];
    const float4* e4 = (const float4*)d_in[1];
    float* out = (float*)d_out;
    const int nRows = in_sizes[0] / DIMV;   // 8192
    const int kRows = in_sizes[1] / DIMV;   // 8192

    static int smemSet = 0;
    if (!smemSet) {
        cudaFuncSetAttribute(vq_mma, cudaFuncAttributeMaxDynamicSharedMemorySize, SMEMSZ);
        smemSet = 1;
    }

    conv_x_kernel<<<nRows / 8, 256>>>(x4);
    conv_e_kernel<<<kRows / 8, 256>>>(e4);
    vq_mma<<<dim3(KCB / BN, nRows / BM), 128, SMEMSZ>>>();
    rescore_kernel<<<nRows / 4, 256>>>(x4, e4, out, nRows);
}